// round 9
// baseline (speedup 1.0000x reference)
#include <cuda_runtime.h>
#include <math.h>

#define B_  2
#define S_  2048
#define D_  1024
#define H_  16
#define HD_ 64
#define M_TOT (B_*S_)   // 4096

// Scratch (device globals — no runtime allocation allowed)
__device__ float g_q[B_*H_*S_*HD_];
__device__ float g_k[B_*H_*S_*HD_];
__device__ float g_v[B_*H_*S_*HD_];
__device__ float g_attn[B_*S_*D_];
__device__ int   g_idx[B_*S_];   // compacted unmasked-key indices per batch
__device__ int   g_kc[B_];       // count of unmasked keys per batch

struct QKVArgs {
    const float* A[3];
    const float* W[3];
    const float* bias[3];
    float*       C[3];
};

// ---------------------------------------------------------------------------
// Mask compaction: one block per batch. Masked keys (mask==0) contribute
// exp(-1e9 - m) == 0.0f exactly in fp32, so skipping them is bit-equivalent.
// ---------------------------------------------------------------------------
__global__ __launch_bounds__(256)
void mask_scan(const int* __restrict__ mask)
{
    __shared__ int cnts[256];
    __shared__ int offs[257];
    const int b   = blockIdx.x;
    const int tid = threadIdx.x;
    const int* m  = mask + b * S_;
    const int base = tid * 8;

    int loc[8];
    int cnt = 0;
    #pragma unroll
    for (int i = 0; i < 8; i++) {
        loc[i] = cnt;
        cnt += (m[base + i] != 0);
    }
    cnts[tid] = cnt;
    __syncthreads();
    if (tid == 0) {
        int s = 0;
        for (int i = 0; i < 256; i++) { offs[i] = s; s += cnts[i]; }
        offs[256] = s;
        g_kc[b] = s;
    }
    __syncthreads();
    const int off = offs[tid];
    #pragma unroll
    for (int i = 0; i < 8; i++)
        if (m[base + i] != 0)
            g_idx[b * S_ + off + loc[i]] = base + i;
}

// ---------------------------------------------------------------------------
// GEMM core: C = A @ W^T + bias. 128x128 tile, BK=16, 256 threads, 8x8 reg
// tile. 2-stage double-buffered smem: prefetch slab k+1 LDGs -> compute slab
// k -> STS slab k+1 -> ONE barrier. SPLIT=1 scatters to [B,H,S,HD].
// ---------------------------------------------------------------------------
template<int SPLIT>
__device__ __forceinline__
void gemm_body(const float* __restrict__ A, const float* __restrict__ W,
               const float* __restrict__ bias, float* __restrict__ C,
               int m0, int n0,
               float (*As)[16][128], float (*Ws)[16][128])
{
    const int K = D_;
    const int tid = threadIdx.x;
    const int ar = tid >> 2;          // 0..63
    const int ac = (tid & 3) * 4;     // 0,4,8,12
    const int ty = tid >> 4;          // 0..15
    const int tx = tid & 15;          // 0..15

    const float* pa0 = &A[(size_t)(m0 + ar)      * K + ac];
    const float* pa1 = &A[(size_t)(m0 + ar + 64) * K + ac];
    const float* pw0 = &W[(size_t)(n0 + ar)      * K + ac];
    const float* pw1 = &W[(size_t)(n0 + ar + 64) * K + ac];

    float acc[8][8];
    #pragma unroll
    for (int i = 0; i < 8; i++)
        #pragma unroll
        for (int j = 0; j < 8; j++) acc[i][j] = 0.f;

    // prologue: stage slab 0
    {
        float4 a0 = *(const float4*)(pa0);
        float4 a1 = *(const float4*)(pa1);
        float4 w0 = *(const float4*)(pw0);
        float4 w1 = *(const float4*)(pw1);
        As[0][ac+0][ar] = a0.x; As[0][ac+1][ar] = a0.y;
        As[0][ac+2][ar] = a0.z; As[0][ac+3][ar] = a0.w;
        As[0][ac+0][ar+64] = a1.x; As[0][ac+1][ar+64] = a1.y;
        As[0][ac+2][ar+64] = a1.z; As[0][ac+3][ar+64] = a1.w;
        Ws[0][ac+0][ar] = w0.x; Ws[0][ac+1][ar] = w0.y;
        Ws[0][ac+2][ar] = w0.z; Ws[0][ac+3][ar] = w0.w;
        Ws[0][ac+0][ar+64] = w1.x; Ws[0][ac+1][ar+64] = w1.y;
        Ws[0][ac+2][ar+64] = w1.z; Ws[0][ac+3][ar+64] = w1.w;
    }
    __syncthreads();

    int cur = 0;
    for (int slab = 0; slab < K/16; slab++) {
        const int nxt = cur ^ 1;
        float4 a0, a1, w0, w1;
        const bool more = (slab < K/16 - 1);
        if (more) {
            const int k1 = (slab + 1) * 16;
            a0 = *(const float4*)(pa0 + k1);
            a1 = *(const float4*)(pa1 + k1);
            w0 = *(const float4*)(pw0 + k1);
            w1 = *(const float4*)(pw1 + k1);
        }

        #pragma unroll
        for (int kk = 0; kk < 16; kk++) {
            float a[8], b[8];
            *(float4*)&a[0] = *(const float4*)&As[cur][kk][ty*8];
            *(float4*)&a[4] = *(const float4*)&As[cur][kk][ty*8+4];
            *(float4*)&b[0] = *(const float4*)&Ws[cur][kk][tx*8];
            *(float4*)&b[4] = *(const float4*)&Ws[cur][kk][tx*8+4];
            #pragma unroll
            for (int i = 0; i < 8; i++)
                #pragma unroll
                for (int j = 0; j < 8; j++)
                    acc[i][j] += a[i] * b[j];
        }

        if (more) {
            As[nxt][ac+0][ar] = a0.x; As[nxt][ac+1][ar] = a0.y;
            As[nxt][ac+2][ar] = a0.z; As[nxt][ac+3][ar] = a0.w;
            As[nxt][ac+0][ar+64] = a1.x; As[nxt][ac+1][ar+64] = a1.y;
            As[nxt][ac+2][ar+64] = a1.z; As[nxt][ac+3][ar+64] = a1.w;
            Ws[nxt][ac+0][ar] = w0.x; Ws[nxt][ac+1][ar] = w0.y;
            Ws[nxt][ac+2][ar] = w0.z; Ws[nxt][ac+3][ar] = w0.w;
            Ws[nxt][ac+0][ar+64] = w1.x; Ws[nxt][ac+1][ar+64] = w1.y;
            Ws[nxt][ac+2][ar+64] = w1.z; Ws[nxt][ac+3][ar+64] = w1.w;
        }
        __syncthreads();
        cur = nxt;
    }

    #pragma unroll
    for (int i = 0; i < 8; i++) {
        int m = m0 + ty*8 + i;
        #pragma unroll
        for (int j4 = 0; j4 < 2; j4++) {
            int n = n0 + tx*8 + j4*4;
            float4 v;
            v.x = acc[i][j4*4+0] + bias[n+0];
            v.y = acc[i][j4*4+1] + bias[n+1];
            v.z = acc[i][j4*4+2] + bias[n+2];
            v.w = acc[i][j4*4+3] + bias[n+3];
            if (SPLIT) {
                int b  = m >> 11;
                int s  = m & (S_ - 1);
                int h  = n >> 6;
                int hd = n & 63;
                *(float4*)&C[(size_t)(((b*H_ + h)*S_) + s) * HD_ + hd] = v;
            } else {
                *(float4*)&C[(size_t)m * D_ + n] = v;
            }
        }
    }
}

// Q/K/V projections batched in one launch (grid.z selects matrix)
__global__ __launch_bounds__(256, 2)
void gemm_qkv(QKVArgs args)
{
    __shared__ float As[2][16][128];
    __shared__ float Ws[2][16][128];
    const int z = blockIdx.z;
    gemm_body<1>(args.A[z], args.W[z], args.bias[z], args.C[z],
                 blockIdx.y * 128, blockIdx.x * 128, As, Ws);
}

__global__ __launch_bounds__(256, 2)
void gemm_out(const float* __restrict__ A, const float* __restrict__ W,
              const float* __restrict__ bias, float* __restrict__ C)
{
    __shared__ float As[2][16][128];
    __shared__ float Ws[2][16][128];
    gemm_body<0>(A, W, bias, C, blockIdx.y * 128, blockIdx.x * 128, As, Ws);
}

// ---------------------------------------------------------------------------
// Flash-style attention over COMPACTED keys (round-8 winner, unchanged).
// ---------------------------------------------------------------------------
#define QSTRIDE 68
#define PSTRIDE 65

__global__ __launch_bounds__(256, 2)
void attn_kernel()
{
    extern __shared__ float sm[];
    float* Qs = sm;
    float* Ks = Qs + 128*QSTRIDE;
    float* Vs = Ks + 64*QSTRIDE;
    float* Ps = Vs + 64*QSTRIDE;

    const int tid = threadIdx.x;
    const int bh  = blockIdx.y;
    const int b   = bh >> 4;
    const int h   = bh & 15;
    const int q0  = blockIdx.x * 128;
    const int qg  = tid >> 3;
    const int c   = tid & 7;

    const float* qbase = g_q + ((size_t)bh * S_ + q0) * HD_;
    const float* kbase = g_k + (size_t)bh * S_ * HD_;
    const float* vbase = g_v + (size_t)bh * S_ * HD_;
    const int*   idxp  = g_idx + b * S_;
    const int    kc    = g_kc[b];
    const int    ntile = (kc + 63) >> 6;

    for (int i = tid; i < 128*16; i += 256) {
        int r = i >> 4, c4 = (i & 15) << 2;
        *(float4*)&Qs[r*QSTRIDE + c4] = *(const float4*)&qbase[r*64 + c4];
    }

    float mrow[4] = {-1e30f, -1e30f, -1e30f, -1e30f};
    float lrow[4] = {0.f, 0.f, 0.f, 0.f};
    float acc[4][8];
    #pragma unroll
    for (int qi = 0; qi < 4; qi++)
        #pragma unroll
        for (int dd = 0; dd < 8; dd++) acc[qi][dd] = 0.f;

    __syncthreads();

    for (int kt = 0; kt < ntile; kt++) {
        const int jb = kt * 64;
        for (int i = tid; i < 64*16; i += 256) {
            int r = i >> 4, c4 = (i & 15) << 2;
            int src = (jb + r < kc) ? idxp[jb + r] : idxp[0];
            *(float4*)&Ks[r*QSTRIDE + c4] = *(const float4*)&kbase[(size_t)src*64 + c4];
            *(float4*)&Vs[r*QSTRIDE + c4] = *(const float4*)&vbase[(size_t)src*64 + c4];
        }
        __syncthreads();

        float s[4][8];
        #pragma unroll
        for (int qi = 0; qi < 4; qi++)
            #pragma unroll
            for (int jj = 0; jj < 8; jj++) s[qi][jj] = 0.f;

        #pragma unroll 4
        for (int d4 = 0; d4 < 64; d4 += 4) {
            float4 qv[4];
            #pragma unroll
            for (int qi = 0; qi < 4; qi++)
                qv[qi] = *(const float4*)&Qs[(qg + 32*qi)*QSTRIDE + d4];
            #pragma unroll
            for (int jj = 0; jj < 8; jj++) {
                float4 kv = *(const float4*)&Ks[(jj*8 + c)*QSTRIDE + d4];
                #pragma unroll
                for (int qi = 0; qi < 4; qi++) {
                    s[qi][jj] = fmaf(qv[qi].x, kv.x, s[qi][jj]);
                    s[qi][jj] = fmaf(qv[qi].y, kv.y, s[qi][jj]);
                    s[qi][jj] = fmaf(qv[qi].z, kv.z, s[qi][jj]);
                    s[qi][jj] = fmaf(qv[qi].w, kv.w, s[qi][jj]);
                }
            }
        }

        #pragma unroll
        for (int jj = 0; jj < 8; jj++) {
            bool ok = (jb + jj*8 + c) < kc;
            #pragma unroll
            for (int qi = 0; qi < 4; qi++)
                s[qi][jj] = ok ? s[qi][jj] * 0.125f : -1.0e9f;
        }

        float t[4];
        #pragma unroll
        for (int qi = 0; qi < 4; qi++) {
            t[qi] = s[qi][0];
            #pragma unroll
            for (int jj = 1; jj < 8; jj++) t[qi] = fmaxf(t[qi], s[qi][jj]);
        }
        #pragma unroll
        for (int o = 1; o < 8; o <<= 1)
            #pragma unroll
            for (int qi = 0; qi < 4; qi++)
                t[qi] = fmaxf(t[qi], __shfl_xor_sync(0xffffffffu, t[qi], o));

        float cor[4], ps[4];
        #pragma unroll
        for (int qi = 0; qi < 4; qi++) {
            float mn = fmaxf(mrow[qi], t[qi]);
            cor[qi] = __expf(mrow[qi] - mn);
            mrow[qi] = mn;
            ps[qi] = 0.f;
            #pragma unroll
            for (int jj = 0; jj < 8; jj++) {
                float p = __expf(s[qi][jj] - mn);
                Ps[(qg + 32*qi)*PSTRIDE + jj*8 + c] = p;
                ps[qi] += p;
            }
        }
        #pragma unroll
        for (int o = 1; o < 8; o <<= 1)
            #pragma unroll
            for (int qi = 0; qi < 4; qi++)
                ps[qi] += __shfl_xor_sync(0xffffffffu, ps[qi], o);
        #pragma unroll
        for (int qi = 0; qi < 4; qi++) {
            lrow[qi] = lrow[qi]*cor[qi] + ps[qi];
            #pragma unroll
            for (int dd = 0; dd < 8; dd++) acc[qi][dd] *= cor[qi];
        }

        __syncthreads();

        #pragma unroll 2
        for (int j = 0; j < 64; j++) {
            float p[4];
            #pragma unroll
            for (int qi = 0; qi < 4; qi++)
                p[qi] = Ps[(qg + 32*qi)*PSTRIDE + j];
            float4 va = *(const float4*)&Vs[j*QSTRIDE + c*8];
            float4 vb = *(const float4*)&Vs[j*QSTRIDE + c*8 + 4];
            #pragma unroll
            for (int qi = 0; qi < 4; qi++) {
                acc[qi][0] = fmaf(p[qi], va.x, acc[qi][0]);
                acc[qi][1] = fmaf(p[qi], va.y, acc[qi][1]);
                acc[qi][2] = fmaf(p[qi], va.z, acc[qi][2]);
                acc[qi][3] = fmaf(p[qi], va.w, acc[qi][3]);
                acc[qi][4] = fmaf(p[qi], vb.x, acc[qi][4]);
                acc[qi][5] = fmaf(p[qi], vb.y, acc[qi][5]);
                acc[qi][6] = fmaf(p[qi], vb.z, acc[qi][6]);
                acc[qi][7] = fmaf(p[qi], vb.w, acc[qi][7]);
            }
        }
        __syncthreads();
    }

    float* outp = g_attn + ((size_t)(b*S_ + q0)) * D_ + h * HD_;
    #pragma unroll
    for (int qi = 0; qi < 4; qi++) {
        float inv = 1.0f / lrow[qi];
        int q = qg + 32*qi;
        float4 o;
        o.x = acc[qi][0]*inv; o.y = acc[qi][1]*inv;
        o.z = acc[qi][2]*inv; o.w = acc[qi][3]*inv;
        *(float4*)&outp[(size_t)q * D_ + c*8] = o;
        o.x = acc[qi][4]*inv; o.y = acc[qi][5]*inv;
        o.z = acc[qi][6]*inv; o.w = acc[qi][7]*inv;
        *(float4*)&outp[(size_t)q * D_ + c*8 + 4] = o;
    }
}

// ---------------------------------------------------------------------------
extern "C" void kernel_launch(void* const* d_in, const int* in_sizes, int n_in,
                              void* d_out, int out_size)
{
    const float* xq  = (const float*)d_in[0];
    const float* xk  = (const float*)d_in[1];
    const float* xv  = (const float*)d_in[2];
    const int*   msk = (const int*)  d_in[3];
    const float* wq  = (const float*)d_in[4];
    const float* bq  = (const float*)d_in[5];
    const float* wk  = (const float*)d_in[6];
    const float* bk  = (const float*)d_in[7];
    const float* wv  = (const float*)d_in[8];
    const float* bv  = (const float*)d_in[9];
    const float* wo  = (const float*)d_in[10];
    const float* bo  = (const float*)d_in[11];

    float *qp, *kp, *vp, *ap;
    cudaGetSymbolAddress((void**)&qp, g_q);
    cudaGetSymbolAddress((void**)&kp, g_k);
    cudaGetSymbolAddress((void**)&vp, g_v);
    cudaGetSymbolAddress((void**)&ap, g_attn);

    const int attn_smem = (128*QSTRIDE + 64*QSTRIDE*2 + 128*PSTRIDE) * (int)sizeof(float);
    static bool attr_set = false;
    if (!attr_set) {
        cudaFuncSetAttribute(attn_kernel,
                             cudaFuncAttributeMaxDynamicSharedMemorySize, attn_smem);
        attr_set = true;
    }

    mask_scan<<<B_, 256>>>(msk);

    QKVArgs qa;
    qa.A[0] = xq; qa.A[1] = xk; qa.A[2] = xv;
    qa.W[0] = wq; qa.W[1] = wk; qa.W[2] = wv;
    qa.bias[0] = bq; qa.bias[1] = bk; qa.bias[2] = bv;
    qa.C[0] = qp; qa.C[1] = kp; qa.C[2] = vp;

    dim3 gq(D_/128, M_TOT/128, 3);   // (8, 32, 3)
    gemm_qkv<<<gq, 256>>>(qa);

    dim3 ga(S_/128, B_*H_);          // (16, 32)
    attn_kernel<<<ga, 256, attn_smem>>>();

    dim3 gg(D_/128, M_TOT/128);      // (8, 32)
    gemm_out<<<gg, 256>>>(ap, wo, bo, (float*)d_out);
}

// round 10
// speedup vs baseline: 1.9015x; 1.9015x over previous
#include <cuda_runtime.h>
#include <math.h>

#define B_  2
#define S_  2048
#define D_  1024
#define H_  16
#define HD_ 64
#define M_TOT (B_*S_)   // 4096

// Scratch (device globals — no runtime allocation allowed)
__device__ float g_q[B_*H_*S_*HD_];
__device__ float g_k[B_*H_*S_*HD_];   // COMPACTED: row i = i-th unmasked key
__device__ float g_v[B_*H_*S_*HD_];   // COMPACTED
__device__ float g_attn[B_*S_*D_];
__device__ int   g_idx[B_*S_];        // compacted unmasked-key indices per batch
__device__ int   g_kc[B_];            // count of unmasked keys per batch

struct QKVArgs {
    const float* A[3];
    const float* W[3];
    const float* bias[3];
    float*       C[3];
};

// ---------------------------------------------------------------------------
// Mask compaction: one block per batch. Masked keys (mask==0) contribute
// exp(-1e9 - m) == 0.0f exactly in fp32, so skipping them is bit-equivalent.
// ---------------------------------------------------------------------------
__global__ __launch_bounds__(256)
void mask_scan(const int* __restrict__ mask)
{
    __shared__ int cnts[256];
    __shared__ int offs[257];
    const int b   = blockIdx.x;
    const int tid = threadIdx.x;
    const int* m  = mask + b * S_;
    const int base = tid * 8;

    int loc[8];
    int cnt = 0;
    #pragma unroll
    for (int i = 0; i < 8; i++) {
        loc[i] = cnt;
        cnt += (m[base + i] != 0);
    }
    cnts[tid] = cnt;
    __syncthreads();
    if (tid == 0) {
        int s = 0;
        for (int i = 0; i < 256; i++) { offs[i] = s; s += cnts[i]; }
        offs[256] = s;
        g_kc[b] = s;
    }
    __syncthreads();
    const int off = offs[tid];
    #pragma unroll
    for (int i = 0; i < 8; i++)
        if (m[base + i] != 0)
            g_idx[b * S_ + off + loc[i]] = base + i;
}

// ---------------------------------------------------------------------------
// GEMM core (round-8 proven version: 2 barriers/slab, no prefetch — measured
// at the FFMA roofline). Row sources passed as precomputed pointers so the
// K/V path can gather through g_idx. 128x128 tile, BK=16, 8x8 reg tile.
// SPLIT=1 scatters C to [B,H,S,HD] (m interpreted as b*2048 + row-in-batch).
// ---------------------------------------------------------------------------
template<int SPLIT>
__device__ __forceinline__
void gemm_body(const float* __restrict__ pa0, const float* __restrict__ pa1,
               const float* __restrict__ W,
               const float* __restrict__ bias, float* __restrict__ C,
               int m0, int n0)
{
    const int K = D_;
    __shared__ float As[16][128];
    __shared__ float Ws[16][128];

    const int tid = threadIdx.x;
    const int ar = tid >> 2;          // 0..63
    const int ac = (tid & 3) * 4;     // 0,4,8,12
    const int ty = tid >> 4;          // 0..15
    const int tx = tid & 15;          // 0..15

    const float* pw0 = &W[(size_t)(n0 + ar)      * K + ac];
    const float* pw1 = &W[(size_t)(n0 + ar + 64) * K + ac];

    float acc[8][8];
    #pragma unroll
    for (int i = 0; i < 8; i++)
        #pragma unroll
        for (int j = 0; j < 8; j++) acc[i][j] = 0.f;

    for (int k0 = 0; k0 < K; k0 += 16) {
        {
            float4 a0 = *(const float4*)(pa0 + k0);
            float4 a1 = *(const float4*)(pa1 + k0);
            float4 w0 = *(const float4*)(pw0 + k0);
            float4 w1 = *(const float4*)(pw1 + k0);
            As[ac+0][ar] = a0.x; As[ac+1][ar] = a0.y;
            As[ac+2][ar] = a0.z; As[ac+3][ar] = a0.w;
            As[ac+0][ar+64] = a1.x; As[ac+1][ar+64] = a1.y;
            As[ac+2][ar+64] = a1.z; As[ac+3][ar+64] = a1.w;
            Ws[ac+0][ar] = w0.x; Ws[ac+1][ar] = w0.y;
            Ws[ac+2][ar] = w0.z; Ws[ac+3][ar] = w0.w;
            Ws[ac+0][ar+64] = w1.x; Ws[ac+1][ar+64] = w1.y;
            Ws[ac+2][ar+64] = w1.z; Ws[ac+3][ar+64] = w1.w;
        }
        __syncthreads();
        #pragma unroll
        for (int kk = 0; kk < 16; kk++) {
            float a[8], b[8];
            *(float4*)&a[0] = *(const float4*)&As[kk][ty*8];
            *(float4*)&a[4] = *(const float4*)&As[kk][ty*8+4];
            *(float4*)&b[0] = *(const float4*)&Ws[kk][tx*8];
            *(float4*)&b[4] = *(const float4*)&Ws[kk][tx*8+4];
            #pragma unroll
            for (int i = 0; i < 8; i++)
                #pragma unroll
                for (int j = 0; j < 8; j++)
                    acc[i][j] += a[i] * b[j];
        }
        __syncthreads();
    }

    #pragma unroll
    for (int i = 0; i < 8; i++) {
        int m = m0 + ty*8 + i;
        #pragma unroll
        for (int j4 = 0; j4 < 2; j4++) {
            int n = n0 + tx*8 + j4*4;
            float4 v;
            v.x = acc[i][j4*4+0] + bias[n+0];
            v.y = acc[i][j4*4+1] + bias[n+1];
            v.z = acc[i][j4*4+2] + bias[n+2];
            v.w = acc[i][j4*4+3] + bias[n+3];
            if (SPLIT) {
                int b  = m >> 11;
                int s  = m & (S_ - 1);
                int h  = n >> 6;
                int hd = n & 63;
                *(float4*)&C[(size_t)(((b*H_ + h)*S_) + s) * HD_ + hd] = v;
            } else {
                *(float4*)&C[(size_t)m * D_ + n] = v;
            }
        }
    }
}

// Q/K/V projections in one launch. z=0: Q over all rows. z=1,2: K/V over the
// COMPACTED unmasked rows only — tiles entirely past kc[b] exit immediately.
__global__ __launch_bounds__(256, 2)
void gemm_qkv(QKVArgs args)
{
    const int z  = blockIdx.z;
    const int m0 = blockIdx.y * 128;
    const int n0 = blockIdx.x * 128;
    const int K  = D_;
    const int ar = threadIdx.x >> 2;
    const int ac = (threadIdx.x & 3) * 4;

    const float* A = args.A[z];
    const float* pa0;
    const float* pa1;
    if (z == 0) {
        pa0 = &A[(size_t)(m0 + ar)      * K + ac];
        pa1 = &A[(size_t)(m0 + ar + 64) * K + ac];
    } else {
        const int b   = m0 >> 11;
        const int kc  = g_kc[b];
        const int lr0 = m0 & (S_ - 1);
        if (lr0 >= kc) return;                 // whole tile past the count
        int lrA = lr0 + ar;        if (lrA >= kc) lrA = kc - 1;
        int lrB = lr0 + ar + 64;   if (lrB >= kc) lrB = kc - 1;
        const int srcA = g_idx[b * S_ + lrA];
        const int srcB = g_idx[b * S_ + lrB];
        pa0 = &A[(size_t)(b * S_ + srcA) * K + ac];
        pa1 = &A[(size_t)(b * S_ + srcB) * K + ac];
    }
    gemm_body<1>(pa0, pa1, args.W[z], args.bias[z], args.C[z], m0, n0);
}

__global__ __launch_bounds__(256, 2)
void gemm_out(const float* __restrict__ A, const float* __restrict__ W,
              const float* __restrict__ bias, float* __restrict__ C)
{
    const int m0 = blockIdx.y * 128;
    const int n0 = blockIdx.x * 128;
    const int ar = threadIdx.x >> 2;
    const int ac = (threadIdx.x & 3) * 4;
    gemm_body<0>(&A[(size_t)(m0 + ar) * D_ + ac],
                 &A[(size_t)(m0 + ar + 64) * D_ + ac],
                 W, bias, C, m0, n0);
}

// ---------------------------------------------------------------------------
// Flash-style attention over COMPACTED K/V (now contiguous — no gather).
// Block tile: 128 queries x 64 keys for one (b,h). 256 threads.
// ---------------------------------------------------------------------------
#define QSTRIDE 68
#define PSTRIDE 65

__global__ __launch_bounds__(256, 2)
void attn_kernel()
{
    extern __shared__ float sm[];
    float* Qs = sm;
    float* Ks = Qs + 128*QSTRIDE;
    float* Vs = Ks + 64*QSTRIDE;
    float* Ps = Vs + 64*QSTRIDE;

    const int tid = threadIdx.x;
    const int bh  = blockIdx.y;
    const int b   = bh >> 4;
    const int h   = bh & 15;
    const int q0  = blockIdx.x * 128;
    const int qg  = tid >> 3;
    const int c   = tid & 7;

    const float* qbase = g_q + ((size_t)bh * S_ + q0) * HD_;
    const float* kbase = g_k + (size_t)bh * S_ * HD_;
    const float* vbase = g_v + (size_t)bh * S_ * HD_;
    const int    kc    = g_kc[b];
    const int    ntile = (kc + 63) >> 6;

    for (int i = tid; i < 128*16; i += 256) {
        int r = i >> 4, c4 = (i & 15) << 2;
        *(float4*)&Qs[r*QSTRIDE + c4] = *(const float4*)&qbase[r*64 + c4];
    }

    float mrow[4] = {-1e30f, -1e30f, -1e30f, -1e30f};
    float lrow[4] = {0.f, 0.f, 0.f, 0.f};
    float acc[4][8];
    #pragma unroll
    for (int qi = 0; qi < 4; qi++)
        #pragma unroll
        for (int dd = 0; dd < 8; dd++) acc[qi][dd] = 0.f;

    __syncthreads();

    for (int kt = 0; kt < ntile; kt++) {
        const int jb = kt * 64;
        // --- load compacted K/V tiles (contiguous, coalesced) ---
        const float* ksrc = kbase + (size_t)jb * 64;
        const float* vsrc = vbase + (size_t)jb * 64;
        for (int i = tid; i < 64*16; i += 256) {
            int r = i >> 4, c4 = (i & 15) << 2;
            *(float4*)&Ks[r*QSTRIDE + c4] = *(const float4*)&ksrc[(size_t)r*64 + c4];
            *(float4*)&Vs[r*QSTRIDE + c4] = *(const float4*)&vsrc[(size_t)r*64 + c4];
        }
        __syncthreads();

        float s[4][8];
        #pragma unroll
        for (int qi = 0; qi < 4; qi++)
            #pragma unroll
            for (int jj = 0; jj < 8; jj++) s[qi][jj] = 0.f;

        #pragma unroll 4
        for (int d4 = 0; d4 < 64; d4 += 4) {
            float4 qv[4];
            #pragma unroll
            for (int qi = 0; qi < 4; qi++)
                qv[qi] = *(const float4*)&Qs[(qg + 32*qi)*QSTRIDE + d4];
            #pragma unroll
            for (int jj = 0; jj < 8; jj++) {
                float4 kv = *(const float4*)&Ks[(jj*8 + c)*QSTRIDE + d4];
                #pragma unroll
                for (int qi = 0; qi < 4; qi++) {
                    s[qi][jj] = fmaf(qv[qi].x, kv.x, s[qi][jj]);
                    s[qi][jj] = fmaf(qv[qi].y, kv.y, s[qi][jj]);
                    s[qi][jj] = fmaf(qv[qi].z, kv.z, s[qi][jj]);
                    s[qi][jj] = fmaf(qv[qi].w, kv.w, s[qi][jj]);
                }
            }
        }

        #pragma unroll
        for (int jj = 0; jj < 8; jj++) {
            bool ok = (jb + jj*8 + c) < kc;
            #pragma unroll
            for (int qi = 0; qi < 4; qi++)
                s[qi][jj] = ok ? s[qi][jj] * 0.125f : -1.0e9f;
        }

        float t[4];
        #pragma unroll
        for (int qi = 0; qi < 4; qi++) {
            t[qi] = s[qi][0];
            #pragma unroll
            for (int jj = 1; jj < 8; jj++) t[qi] = fmaxf(t[qi], s[qi][jj]);
        }
        #pragma unroll
        for (int o = 1; o < 8; o <<= 1)
            #pragma unroll
            for (int qi = 0; qi < 4; qi++)
                t[qi] = fmaxf(t[qi], __shfl_xor_sync(0xffffffffu, t[qi], o));

        float cor[4], ps[4];
        #pragma unroll
        for (int qi = 0; qi < 4; qi++) {
            float mn = fmaxf(mrow[qi], t[qi]);
            cor[qi] = __expf(mrow[qi] - mn);
            mrow[qi] = mn;
            ps[qi] = 0.f;
            #pragma unroll
            for (int jj = 0; jj < 8; jj++) {
                float p = __expf(s[qi][jj] - mn);
                Ps[(qg + 32*qi)*PSTRIDE + jj*8 + c] = p;
                ps[qi] += p;
            }
        }
        #pragma unroll
        for (int o = 1; o < 8; o <<= 1)
            #pragma unroll
            for (int qi = 0; qi < 4; qi++)
                ps[qi] += __shfl_xor_sync(0xffffffffu, ps[qi], o);
        #pragma unroll
        for (int qi = 0; qi < 4; qi++) {
            lrow[qi] = lrow[qi]*cor[qi] + ps[qi];
            #pragma unroll
            for (int dd = 0; dd < 8; dd++) acc[qi][dd] *= cor[qi];
        }

        __syncthreads();

        #pragma unroll 2
        for (int j = 0; j < 64; j++) {
            float p[4];
            #pragma unroll
            for (int qi = 0; qi < 4; qi++)
                p[qi] = Ps[(qg + 32*qi)*PSTRIDE + j];
            float4 va = *(const float4*)&Vs[j*QSTRIDE + c*8];
            float4 vb = *(const float4*)&Vs[j*QSTRIDE + c*8 + 4];
            #pragma unroll
            for (int qi = 0; qi < 4; qi++) {
                acc[qi][0] = fmaf(p[qi], va.x, acc[qi][0]);
                acc[qi][1] = fmaf(p[qi], va.y, acc[qi][1]);
                acc[qi][2] = fmaf(p[qi], va.z, acc[qi][2]);
                acc[qi][3] = fmaf(p[qi], va.w, acc[qi][3]);
                acc[qi][4] = fmaf(p[qi], vb.x, acc[qi][4]);
                acc[qi][5] = fmaf(p[qi], vb.y, acc[qi][5]);
                acc[qi][6] = fmaf(p[qi], vb.z, acc[qi][6]);
                acc[qi][7] = fmaf(p[qi], vb.w, acc[qi][7]);
            }
        }
        __syncthreads();
    }

    float* outp = g_attn + ((size_t)(b*S_ + q0)) * D_ + h * HD_;
    #pragma unroll
    for (int qi = 0; qi < 4; qi++) {
        float inv = 1.0f / lrow[qi];
        int q = qg + 32*qi;
        float4 o;
        o.x = acc[qi][0]*inv; o.y = acc[qi][1]*inv;
        o.z = acc[qi][2]*inv; o.w = acc[qi][3]*inv;
        *(float4*)&outp[(size_t)q * D_ + c*8] = o;
        o.x = acc[qi][4]*inv; o.y = acc[qi][5]*inv;
        o.z = acc[qi][6]*inv; o.w = acc[qi][7]*inv;
        *(float4*)&outp[(size_t)q * D_ + c*8 + 4] = o;
    }
}

// ---------------------------------------------------------------------------
extern "C" void kernel_launch(void* const* d_in, const int* in_sizes, int n_in,
                              void* d_out, int out_size)
{
    const float* xq  = (const float*)d_in[0];
    const float* xk  = (const float*)d_in[1];
    const float* xv  = (const float*)d_in[2];
    const int*   msk = (const int*)  d_in[3];
    const float* wq  = (const float*)d_in[4];
    const float* bq  = (const float*)d_in[5];
    const float* wk  = (const float*)d_in[6];
    const float* bk  = (const float*)d_in[7];
    const float* wv  = (const float*)d_in[8];
    const float* bv  = (const float*)d_in[9];
    const float* wo  = (const float*)d_in[10];
    const float* bo  = (const float*)d_in[11];

    float *qp, *kp, *vp, *ap;
    cudaGetSymbolAddress((void**)&qp, g_q);
    cudaGetSymbolAddress((void**)&kp, g_k);
    cudaGetSymbolAddress((void**)&vp, g_v);
    cudaGetSymbolAddress((void**)&ap, g_attn);

    const int attn_smem = (128*QSTRIDE + 64*QSTRIDE*2 + 128*PSTRIDE) * (int)sizeof(float);
    static bool attr_set = false;
    if (!attr_set) {
        cudaFuncSetAttribute(attn_kernel,
                             cudaFuncAttributeMaxDynamicSharedMemorySize, attn_smem);
        attr_set = true;
    }

    mask_scan<<<B_, 256>>>(msk);

    QKVArgs qa;
    qa.A[0] = xq; qa.A[1] = xk; qa.A[2] = xv;
    qa.W[0] = wq; qa.W[1] = wk; qa.W[2] = wv;
    qa.bias[0] = bq; qa.bias[1] = bk; qa.bias[2] = bv;
    qa.C[0] = qp; qa.C[1] = kp; qa.C[2] = vp;

    dim3 gq(D_/128, M_TOT/128, 3);   // (8, 32, 3)
    gemm_qkv<<<gq, 256>>>(qa);

    dim3 ga(S_/128, B_*H_);          // (16, 32)
    attn_kernel<<<ga, 256, attn_smem>>>();

    dim3 gg(D_/128, M_TOT/128);      // (8, 32)
    gemm_out<<<gg, 256>>>(ap, wo, bo, (float*)d_out);
}